// round 16
// baseline (speedup 1.0000x reference)
#include <cuda_runtime.h>
#include <cstdint>

typedef unsigned long long ULL;

#define B_   64
#define S_   1024
#define I_   1024
#define H_   1024
#define SH_  (S_ * H_)   // 1048576

// ---- helpers ----
__device__ __forceinline__ void cp_async16(uint32_t smem_addr, const void* gptr) {
    asm volatile("cp.async.cg.shared.global [%0], [%1], 16;"
                 :: "r"(smem_addr), "l"(gptr));
}
__device__ __forceinline__ uint32_t smem_u32(const void* p) {
    return (uint32_t)__cvta_generic_to_shared(p);
}
// pack: low half = bf16(v0), high half = bf16(v1)
__device__ __forceinline__ uint32_t pack_bf16(float v0, float v1) {
    uint32_t r;
    asm("cvt.rn.bf16x2.f32 %0, %1, %2;" : "=r"(r) : "f"(v1), "f"(v0));
    return r;
}
__device__ __forceinline__ void ldsm_x4(uint32_t& r0, uint32_t& r1,
                                        uint32_t& r2, uint32_t& r3, uint32_t a) {
    asm volatile("ldmatrix.sync.aligned.m8n8.x4.shared.b16 {%0,%1,%2,%3}, [%4];"
                 : "=r"(r0), "=r"(r1), "=r"(r2), "=r"(r3) : "r"(a));
}
__device__ __forceinline__ void ldsm_x2(uint32_t& r0, uint32_t& r1, uint32_t a) {
    asm volatile("ldmatrix.sync.aligned.m8n8.x2.shared.b16 {%0,%1}, [%2];"
                 : "=r"(r0), "=r"(r1) : "r"(a));
}
__device__ __forceinline__ void mma_bf16(float& c0, float& c1, float& c2, float& c3,
                                         uint32_t a0, uint32_t a1, uint32_t a2, uint32_t a3,
                                         uint32_t b0, uint32_t b1) {
    asm volatile("mma.sync.aligned.m16n8k16.row.col.f32.bf16.bf16.f32 "
                 "{%0,%1,%2,%3}, {%4,%5,%6,%7}, {%8,%9}, {%0,%1,%2,%3};"
                 : "+f"(c0), "+f"(c1), "+f"(c2), "+f"(c3)
                 : "r"(a0), "r"(a1), "r"(a2), "r"(a3), "r"(b0), "r"(b1));
}
#define HALF_BAR(id) asm volatile("bar.sync %0, 128;" :: "r"(id) : "memory")

// ============================================================================
// Static scratch.
// ============================================================================
__device__ unsigned g_xhi[33554432];   // x split-bf16 (wx path)
__device__ unsigned g_xlo[33554432];
__device__ unsigned g_whi[524288];     // Wih split-bf16
__device__ unsigned g_wlo[524288];
// h state: TRIPLE buffered (mod 3) — quarter-granular waiting means only
// two-hop transitivity protects overwrites; buf written at step s was last
// read at step s-2, and all CTAs are provably past step s-2. [buf][hi/lo].
__device__ unsigned g_hb[3][2][32768];

// ============================================================================
// Convert fp32 -> (hi, lo) bf16 pairs. which: 0 = x, 1 = W. (wx path)
// ============================================================================
__global__ void cvt_split(const float* __restrict__ src, int which, int n4)
{
    unsigned* hi = which ? g_whi : g_xhi;
    unsigned* lo = which ? g_wlo : g_xlo;
    int stride = gridDim.x * blockDim.x;
    for (int i = blockIdx.x * blockDim.x + threadIdx.x; i < n4; i += stride) {
        float4 v = ((const float4*)src)[i];
        uint32_t h0 = pack_bf16(v.x, v.y);
        uint32_t h1 = pack_bf16(v.z, v.w);
        float l0 = v.x - __uint_as_float(h0 << 16);
        float l1 = v.y - __uint_as_float(h0 & 0xFFFF0000u);
        float l2 = v.z - __uint_as_float(h1 << 16);
        float l3 = v.w - __uint_as_float(h1 & 0xFFFF0000u);
        hi[2 * i]     = h0;
        hi[2 * i + 1] = h1;
        lo[2 * i]     = pack_bf16(l0, l1);
        lo[2 * i + 1] = pack_bf16(l2, l3);
    }
}

// ============================================================================
// wx_mma (unchanged from R13/R14 — known good).
// ============================================================================
#define STG_BYTES 40960
#define A_LO_OFF  10240
#define B_OFF     20480
#define B_LO_OFF  30720

__global__ __launch_bounds__(512, 1)
void wx_mma(const float* __restrict__ bias, float* __restrict__ y)
{
    extern __shared__ __align__(16) char smem[];
    const uint32_t sbase = smem_u32(smem);

    const int tid  = threadIdx.x;
    const int wid  = tid >> 5;
    const int lane = tid & 31;
    const int g    = lane >> 2;
    const int t    = lane & 3;
    const int wm   = wid & 3;
    const int wn   = wid >> 2;
    const int m0   = blockIdx.y * 128;
    const int n0   = blockIdx.x * 128;

    float acc[2][4][4];
#pragma unroll
    for (int mf = 0; mf < 2; mf++)
#pragma unroll
        for (int nf = 0; nf < 4; nf++)
#pragma unroll
            for (int c = 0; c < 4; c++) acc[mf][nf][c] = 0.0f;

    auto issue = [&](int st) {
        const uint32_t d = sbase + (st & 1) * STG_BYTES;
        const int k0 = st * 32;
#pragma unroll
        for (int r = 0; r < 2; r++) {
            int id   = tid + 512 * r;
            int part = id >> 9;
            int rem  = id & 511;
            int row  = rem >> 2;
            int seg  = rem & 3;
            const unsigned* srcb = part ? g_xlo : g_xhi;
            const char* src = (const char*)(srcb +
                ((size_t)(m0 + row) * 1024 + k0) / 2) + seg * 16;
            cp_async16(d + part * A_LO_OFF + row * 80 + seg * 16, src);
        }
#pragma unroll
        for (int r = 0; r < 2; r++) {
            int id   = tid + 512 * r;
            int part = id >> 9;
            int rem  = id & 511;
            int row  = rem >> 2;
            int seg  = rem & 3;
            const unsigned* srcb = part ? g_wlo : g_whi;
            const char* src = (const char*)(srcb +
                ((size_t)(n0 + row) * 1024 + k0) / 2) + seg * 16;
            cp_async16(d + B_OFF + part * 10240 + row * 80 + seg * 16, src);
        }
        asm volatile("cp.async.commit_group;" ::: "memory");
    };

    issue(0);
    for (int i = 0; i < 32; i++) {
        if (i + 1 < 32) {
            issue(i + 1);
            asm volatile("cp.async.wait_group 1;" ::: "memory");
        } else {
            asm volatile("cp.async.wait_group 0;" ::: "memory");
        }
        __syncthreads();

        const char* sm  = smem + (i & 1) * STG_BYTES;
        const char* Ahi = sm;
        const char* Alo = sm + A_LO_OFF;
        const char* Bhi = sm + B_OFF;
        const char* Blo = sm + B_LO_OFF;

#pragma unroll
        for (int ks = 0; ks < 32; ks += 16) {
            const int colb = (ks + t * 2) * 2;
            uint32_t ah[2][4], al[2][4];
#pragma unroll
            for (int mf = 0; mf < 2; mf++) {
                int r0 = (wm * 32 + mf * 16 + g) * 80;
                int r1 = r0 + 8 * 80;
                ah[mf][0] = *(const uint32_t*)(Ahi + r0 + colb);
                ah[mf][1] = *(const uint32_t*)(Ahi + r1 + colb);
                ah[mf][2] = *(const uint32_t*)(Ahi + r0 + colb + 16);
                ah[mf][3] = *(const uint32_t*)(Ahi + r1 + colb + 16);
                al[mf][0] = *(const uint32_t*)(Alo + r0 + colb);
                al[mf][1] = *(const uint32_t*)(Alo + r1 + colb);
                al[mf][2] = *(const uint32_t*)(Alo + r0 + colb + 16);
                al[mf][3] = *(const uint32_t*)(Alo + r1 + colb + 16);
            }
            uint32_t bh[4][2], bl[4][2];
#pragma unroll
            for (int nf = 0; nf < 4; nf++) {
                int nr = (wn * 32 + nf * 8 + g) * 80;
                bh[nf][0] = *(const uint32_t*)(Bhi + nr + colb);
                bh[nf][1] = *(const uint32_t*)(Bhi + nr + colb + 16);
                bl[nf][0] = *(const uint32_t*)(Blo + nr + colb);
                bl[nf][1] = *(const uint32_t*)(Blo + nr + colb + 16);
            }
#pragma unroll
            for (int mf = 0; mf < 2; mf++)
#pragma unroll
                for (int nf = 0; nf < 4; nf++) {
                    float* c = acc[mf][nf];
                    mma_bf16(c[0], c[1], c[2], c[3],
                             ah[mf][0], ah[mf][1], ah[mf][2], ah[mf][3],
                             bh[nf][0], bh[nf][1]);
                    mma_bf16(c[0], c[1], c[2], c[3],
                             al[mf][0], al[mf][1], al[mf][2], al[mf][3],
                             bh[nf][0], bh[nf][1]);
                    mma_bf16(c[0], c[1], c[2], c[3],
                             ah[mf][0], ah[mf][1], ah[mf][2], ah[mf][3],
                             bl[nf][0], bl[nf][1]);
                }
        }
        __syncthreads();
    }

#pragma unroll
    for (int mf = 0; mf < 2; mf++) {
        int m = m0 + wm * 32 + mf * 16 + g;
#pragma unroll
        for (int nf = 0; nf < 4; nf++) {
            int n = n0 + wn * 32 + nf * 8 + t * 2;
            float2 bv = *(const float2*)(bias + n);
            float* c = acc[mf][nf];
            *(float2*)(y + (size_t)m * H_ + n) =
                make_float2(c[0] + bv.x, c[1] + bv.y);
            *(float2*)(y + (size_t)(m + 8) * H_ + n) =
                make_float2(c[2] + bv.x, c[3] + bv.y);
        }
    }
}

// ============================================================================
// Sync: entry rendezvous + QUARTER-granular monotonic producer counters.
// Quarter qc of bg counts arrivals from producer CTAs ft in [8qc, 8qc+8)
// (whose features are K-range [256qc, 256qc+256)). 8 arrivals per step.
// Consumer half kw polls quarter 2kw before staging chunk 0 and quarter
// 2kw+1 before chunk 1. Bases are read before the rendezvous arrive.
// ============================================================================
__device__ unsigned g_cnt[4 * 32];
__device__ unsigned g_gen[4 * 32];
__device__ unsigned g_qstep[4 * 4 * 32];   // (bg*4 + qc)*32

__device__ __forceinline__ void rendezvous(int bg, unsigned nb) {
    __syncthreads();
    if (threadIdx.x == 0) {
        unsigned* cnt = &g_cnt[bg * 32];
        unsigned* gen = &g_gen[bg * 32];
        unsigned g;
        asm volatile("ld.global.acquire.gpu.u32 %0, [%1];" : "=r"(g) : "l"(gen));
        unsigned prev;
        asm volatile("atom.global.acq_rel.gpu.add.u32 %0, [%1], %2;"
                     : "=r"(prev) : "l"(cnt), "r"(1u));
        if (prev == nb - 1) {
            asm volatile("st.global.relaxed.gpu.u32 [%0], %1;" :: "l"(cnt), "r"(0u));
            asm volatile("st.global.release.gpu.u32 [%0], %1;" :: "l"(gen), "r"(g + 1u));
        } else {
            unsigned cur;
            do {
                asm volatile("ld.global.acquire.gpu.u32 %0, [%1];" : "=r"(cur) : "l"(gen));
            } while (cur == g);
        }
    }
    __syncthreads();
}

__device__ __forceinline__ void poll_ge(const unsigned* p, unsigned tgt) {
    unsigned v;
    do {
        asm volatile("ld.global.acquire.gpu.u32 %0, [%1];" : "=r"(v) : "l"(p));
    } while ((int)(v - tgt) < 0);
}

// ============================================================================
// Persistent recurrence, split-bf16 HMMA, two half-pipelines, quarter sync.
// ============================================================================
#define WHI_OFF 0
#define WLO_OFF 66048
#define HHI_OFF 132096
#define HLO_OFF 165120
#define RED_OFF 198144
#define RNN_SMEM 200192

__global__ __launch_bounds__(256, 1)
void rnn_persistent(const float* __restrict__ h0,
                    const float* __restrict__ Whh,
                    const float* __restrict__ bias,
                    float* __restrict__ y,
                    float* __restrict__ hlast)
{
    extern __shared__ __align__(16) char smem[];
    const uint32_t sb = smem_u32(smem);
    __shared__ unsigned sh_base4[4];

    const int tid  = threadIdx.x;
    const int w    = tid >> 5;
    const int lane = tid & 31;
    const int nf   = w & 3;
    const int kw   = w >> 2;
    const int htid = tid & 127;
    const int ft_id = blockIdx.x;
    const int bg_id = blockIdx.y;
    const int ftile = ft_id * 32;
    const int bg    = bg_id * 16;

    unsigned* qbase = &g_qstep[bg_id * 4 * 32];
    if (tid == 0) {
#pragma unroll
        for (int i = 0; i < 4; i++) {
            unsigned b;
            asm volatile("ld.global.relaxed.gpu.u32 %0, [%1];"
                         : "=r"(b) : "l"(qbase + i * 32));
            sh_base4[i] = b;
        }
    }

    // ---- one-time: Whh slice -> smem split bf16, 2064B padded rows ----
    {
        const int r = tid >> 3;
        const int part = tid & 7;
        const float* src = Whh + (size_t)(ftile + r) * H_ + part * 128;
        char* dhi = smem + WHI_OFF + r * 2064 + part * 256;
        char* dlo = smem + WLO_OFF + r * 2064 + part * 256;
#pragma unroll
        for (int u = 0; u < 32; u++) {
            float4 v = *(const float4*)(src + u * 4);
            uint32_t h0p = pack_bf16(v.x, v.y);
            uint32_t h1p = pack_bf16(v.z, v.w);
            float l0 = v.x - __uint_as_float(h0p << 16);
            float l1 = v.y - __uint_as_float(h0p & 0xFFFF0000u);
            float l2 = v.z - __uint_as_float(h1p << 16);
            float l3 = v.w - __uint_as_float(h1p & 0xFFFF0000u);
            *(uint2*)(dhi + u * 8) = make_uint2(h0p, h1p);
            *(uint2*)(dlo + u * 8) = make_uint2(pack_bf16(l0, l1), pack_bf16(l2, l3));
        }
    }

    // ---- one-time: ft0 CTA converts h0 (its bg's 16 rows) into g_hb[0] ----
    if (ft_id == 0) {
        const int r = tid >> 4;
        const int part = tid & 15;
        const float* src = h0 + (size_t)(bg + r) * H_ + part * 64;
        unsigned* dhi = &g_hb[0][0][(bg + r) * 512 + part * 32];
        unsigned* dlo = &g_hb[0][1][(bg + r) * 512 + part * 32];
#pragma unroll
        for (int u = 0; u < 16; u++) {
            float4 v = *(const float4*)(src + u * 4);
            uint32_t h0p = pack_bf16(v.x, v.y);
            uint32_t h1p = pack_bf16(v.z, v.w);
            float l0 = v.x - __uint_as_float(h0p << 16);
            float l1 = v.y - __uint_as_float(h0p & 0xFFFF0000u);
            float l2 = v.z - __uint_as_float(h1p << 16);
            float l3 = v.w - __uint_as_float(h1p & 0xFFFF0000u);
            *(uint2*)(dhi + u * 2) = make_uint2(h0p, h1p);
            *(uint2*)(dlo + u * 2) = make_uint2(pack_bf16(l0, l1), pack_bf16(l2, l3));
        }
    }

    // ---- output mapping ----
    const int mq = lane >> 2;
    const int q  = lane & 3;
    const int fgn  = ftile + nf * 8 + q * 2;
    const int rowA = bg + mq;
    const int rowB = bg + mq + 8;
    float2 bias2 = *(const float2*)(bias + fgn);
    float* yA = y + (size_t)rowA * SH_ + fgn;
    float* yB = y + (size_t)rowB * SH_ + fgn;
    float2 wx2 = (kw == 0) ? *(float2*)yA : *(float2*)yB;

    // ---- ldmatrix base addresses ----
    const uint32_t aHiB = sb + HHI_OFF + (uint32_t)(lane & 15) * 2064 +
                          (uint32_t)((lane >> 4) << 4);
    const uint32_t aLoB = aHiB + (HLO_OFF - HHI_OFF);
    const int bl = lane & 15;
    const uint32_t bHiB = sb + WHI_OFF +
                          (uint32_t)(nf * 8 + (bl & 7)) * 2064 +
                          (uint32_t)(((bl >> 3) & 1) << 4);
    const uint32_t bLoB = bHiB + (WLO_OFF - WHI_OFF);

    float2* bufA = (float2*)(smem + RED_OFF);        // kw0 -> kw1 (rowB partials)
    float2* bufB = bufA + 128;                       // kw1 -> kw0 (rowA partials)
    const int slot = (nf * 8 + mq) * 4 + q;

    const int kbase = kw * 512;
    const int barid = 1 + kw;

    rendezvous(bg_id, 32);   // anchors bases; h0 conversion + W smem visible
    const unsigned bq0 = sh_base4[2 * kw];
    const unsigned bq1 = sh_base4[2 * kw + 1];
    const unsigned* qc0p = qbase + (2 * kw) * 32;
    const unsigned* qc1p = qbase + (2 * kw + 1) * 32;
    unsigned* my_q = qbase + (ft_id >> 3) * 32;

    int p = 0;   // h read buffer = s mod 3
    for (int s = 0; s < S_; s++) {
        const int p1 = (p == 2) ? 0 : p + 1;

        // ---- chunk 0: poll its 8 producers, then stage ----
        if (s > 0) {
            if (htid == 0) poll_ge(qc0p, bq0 + 8u * (unsigned)s);
            HALF_BAR(barid);
        }
        {
            const int koffB = kbase * 2;
#pragma unroll
            for (int r = 0; r < 8; r++) {
                int idx   = r * 128 + htid;
                int split = idx >> 9;
                int rem   = idx & 511;
                int row   = rem >> 5;
                int seg   = rem & 31;
                const char* src = (const char*)g_hb[p][split] +
                                  (size_t)(bg + row) * 2048 + koffB + seg * 16;
                cp_async16(sb + (split ? HLO_OFF : HHI_OFF) +
                           (uint32_t)(row * 2064 + koffB + seg * 16), src);
            }
            asm volatile("cp.async.commit_group;" ::: "memory");
        }
        // ---- chunk 1: poll its 8 producers, then stage ----
        if (s > 0) {
            if (htid == 0) poll_ge(qc1p, bq1 + 8u * (unsigned)s);
            HALF_BAR(barid);
        }
        {
            const int koffB = (kbase + 256) * 2;
#pragma unroll
            for (int r = 0; r < 8; r++) {
                int idx   = r * 128 + htid;
                int split = idx >> 9;
                int rem   = idx & 511;
                int row   = rem >> 5;
                int seg   = rem & 31;
                const char* src = (const char*)g_hb[p][split] +
                                  (size_t)(bg + row) * 2048 + koffB + seg * 16;
                cp_async16(sb + (split ? HLO_OFF : HHI_OFF) +
                           (uint32_t)(row * 2064 + koffB + seg * 16), src);
            }
            asm volatile("cp.async.commit_group;" ::: "memory");
        }

        float c0 = 0.f, c1 = 0.f, c2 = 0.f, c3 = 0.f;

#pragma unroll
        for (int c = 0; c < 2; c++) {
            if (c == 0) asm volatile("cp.async.wait_group 1;" ::: "memory");
            else        asm volatile("cp.async.wait_group 0;" ::: "memory");
            HALF_BAR(barid);

            const int kc = kbase + c * 256;
#pragma unroll 4
            for (int i = 0; i < 16; i++) {
                const uint32_t kb = (uint32_t)(kc + i * 16) * 2;
                uint32_t ah0, ah1, ah2, ah3, al0, al1, al2, al3;
                uint32_t bh0, bh1, blo0, blo1;
                ldsm_x4(ah0, ah1, ah2, ah3, aHiB + kb);
                ldsm_x4(al0, al1, al2, al3, aLoB + kb);
                ldsm_x2(bh0, bh1, bHiB + kb);
                ldsm_x2(blo0, blo1, bLoB + kb);
                mma_bf16(c0, c1, c2, c3, ah0, ah1, ah2, ah3, bh0, bh1);
                mma_bf16(c0, c1, c2, c3, al0, al1, al2, al3, bh0, bh1);
                mma_bf16(c0, c1, c2, c3, ah0, ah1, ah2, ah3, blo0, blo1);
            }
        }

        // ---- symmetric partial exchange ----
        if (kw == 0) bufA[slot] = make_float2(c2, c3);
        else         bufB[slot] = make_float2(c0, c1);
        __syncthreads();

        // ---- writeback: kw0 rowA, kw1 rowB; g_hb stores first ----
        if (kw == 0) {
            float2 o = bufB[slot];
            float v0 = tanhf(wx2.x + c0 + o.x + bias2.x);
            float v1 = tanhf(wx2.y + c1 + o.y + bias2.y);
            uint32_t hp = pack_bf16(v0, v1);
            float l0 = v0 - __uint_as_float(hp << 16);
            float l1 = v1 - __uint_as_float(hp & 0xFFFF0000u);
            g_hb[p1][0][rowA * 512 + (fgn >> 1)] = hp;
            g_hb[p1][1][rowA * 512 + (fgn >> 1)] = pack_bf16(l0, l1);
            float* ysA = yA + (size_t)s * H_;
            *(float2*)ysA = make_float2(v0, v1);
            if (s == S_ - 1)
                *(float2*)(hlast + (size_t)rowA * H_ + fgn) = make_float2(v0, v1);
            else
                wx2 = *(float2*)(ysA + H_);
        } else {
            float2 o = bufA[slot];
            float v0 = tanhf(wx2.x + c2 + o.x + bias2.x);
            float v1 = tanhf(wx2.y + c3 + o.y + bias2.y);
            uint32_t hp = pack_bf16(v0, v1);
            float l0 = v0 - __uint_as_float(hp << 16);
            float l1 = v1 - __uint_as_float(hp & 0xFFFF0000u);
            g_hb[p1][0][rowB * 512 + (fgn >> 1)] = hp;
            g_hb[p1][1][rowB * 512 + (fgn >> 1)] = pack_bf16(l0, l1);
            float* ysB = yB + (size_t)s * H_;
            *(float2*)ysB = make_float2(v0, v1);
            if (s == S_ - 1)
                *(float2*)(hlast + (size_t)rowB * H_ + fgn) = make_float2(v0, v1);
            else
                wx2 = *(float2*)(ysB + H_);
        }

        // ---- publish: fire-and-forget arrive to this CTA's quarter ----
        __syncthreads();   // both halves' g_hb stores done
        if (tid == 0 && s < S_ - 1) {
            asm volatile("red.global.release.gpu.add.u32 [%0], %1;"
                         :: "l"(my_q), "r"(1u) : "memory");
        }

        p = p1;
    }
}

// ============================================================================
// Launch: 4 graph nodes. Inputs: x, h, Wih_w, Wih_b, Whh_w, Whh_b.
// Output: y [B,S,H] followed by h_last [B,H].
// ============================================================================
extern "C" void kernel_launch(void* const* d_in, const int* in_sizes, int n_in,
                              void* d_out, int out_size)
{
    const float* x     = (const float*)d_in[0];
    const float* h0    = (const float*)d_in[1];
    const float* Wih_w = (const float*)d_in[2];
    const float* Wih_b = (const float*)d_in[3];
    const float* Whh_w = (const float*)d_in[4];
    const float* Whh_b = (const float*)d_in[5];

    float* y     = (float*)d_out;
    float* hlast = y + (size_t)B_ * S_ * H_;

    const int mma_smem = 2 * STG_BYTES;   // 81920
    cudaFuncSetAttribute(wx_mma, cudaFuncAttributeMaxDynamicSharedMemorySize,
                         mma_smem);
    cudaFuncSetAttribute(rnn_persistent,
                         cudaFuncAttributeMaxDynamicSharedMemorySize, RNN_SMEM);

    cvt_split<<<8192, 256>>>(x, 0, 16777216);      // x: 16M float4
    cvt_split<<<1024, 256>>>(Wih_w, 1, 262144);    // W: 256K float4
    wx_mma<<<dim3(8, 512), 512, mma_smem>>>(Wih_b, y);
    rnn_persistent<<<dim3(32, 4), 256, RNN_SMEM>>>(h0, Whh_w, Whh_b, y, hlast);
}

// round 17
// speedup vs baseline: 1.0834x; 1.0834x over previous
#include <cuda_runtime.h>
#include <cuda_fp16.h>
#include <cstdint>

typedef unsigned long long ULL;

#define B_   64
#define S_   1024
#define I_   1024
#define H_   1024
#define SH_  (S_ * H_)   // 1048576

// ---- helpers ----
__device__ __forceinline__ void cp_async16(uint32_t smem_addr, const void* gptr) {
    asm volatile("cp.async.cg.shared.global [%0], [%1], 16;"
                 :: "r"(smem_addr), "l"(gptr));
}
__device__ __forceinline__ uint32_t smem_u32(const void* p) {
    return (uint32_t)__cvta_generic_to_shared(p);
}
// pack: low half = bf16(v0), high half = bf16(v1)
__device__ __forceinline__ uint32_t pack_bf16(float v0, float v1) {
    uint32_t r;
    asm("cvt.rn.bf16x2.f32 %0, %1, %2;" : "=r"(r) : "f"(v1), "f"(v0));
    return r;
}
__device__ __forceinline__ uint32_t pack_f16(float v0, float v1) {
    __half2 h = __floats2half2_rn(v0, v1);   // .x = v0 (low), .y = v1 (high)
    return *reinterpret_cast<uint32_t*>(&h);
}
__device__ __forceinline__ void ldsm_x4(uint32_t& r0, uint32_t& r1,
                                        uint32_t& r2, uint32_t& r3, uint32_t a) {
    asm volatile("ldmatrix.sync.aligned.m8n8.x4.shared.b16 {%0,%1,%2,%3}, [%4];"
                 : "=r"(r0), "=r"(r1), "=r"(r2), "=r"(r3) : "r"(a));
}
__device__ __forceinline__ void ldsm_x2(uint32_t& r0, uint32_t& r1, uint32_t a) {
    asm volatile("ldmatrix.sync.aligned.m8n8.x2.shared.b16 {%0,%1}, [%2];"
                 : "=r"(r0), "=r"(r1) : "r"(a));
}
__device__ __forceinline__ void mma_bf16(float& c0, float& c1, float& c2, float& c3,
                                         uint32_t a0, uint32_t a1, uint32_t a2, uint32_t a3,
                                         uint32_t b0, uint32_t b1) {
    asm volatile("mma.sync.aligned.m16n8k16.row.col.f32.bf16.bf16.f32 "
                 "{%0,%1,%2,%3}, {%4,%5,%6,%7}, {%8,%9}, {%0,%1,%2,%3};"
                 : "+f"(c0), "+f"(c1), "+f"(c2), "+f"(c3)
                 : "r"(a0), "r"(a1), "r"(a2), "r"(a3), "r"(b0), "r"(b1));
}
__device__ __forceinline__ void mma_f16(float& c0, float& c1, float& c2, float& c3,
                                        uint32_t a0, uint32_t a1, uint32_t a2, uint32_t a3,
                                        uint32_t b0, uint32_t b1) {
    asm volatile("mma.sync.aligned.m16n8k16.row.col.f32.f16.f16.f32 "
                 "{%0,%1,%2,%3}, {%4,%5,%6,%7}, {%8,%9}, {%0,%1,%2,%3};"
                 : "+f"(c0), "+f"(c1), "+f"(c2), "+f"(c3)
                 : "r"(a0), "r"(a1), "r"(a2), "r"(a3), "r"(b0), "r"(b1));
}
#define HALF_BAR(id) asm volatile("bar.sync %0, 128;" :: "r"(id) : "memory")

// ============================================================================
// Static scratch.
// ============================================================================
__device__ unsigned g_xhi[33554432];   // x fp16-hi pairs (wx path)
__device__ unsigned g_xlo[33554432];   // x fp16-lo pairs
__device__ unsigned g_whi[524288];     // Wih single fp16 pairs
// h state: double-buffered (R14 semantics: full-group wait => safe).
__device__ unsigned g_hb[2][2][32768]; // [parity][hi/lo][64 rows x 512 u32]

// ============================================================================
// Convert fp32 -> fp16 pairs. which 0: x -> (hi, lo). which 1: W -> hi only.
// ============================================================================
__global__ void cvt_split(const float* __restrict__ src, int which, int n4)
{
    int stride = gridDim.x * blockDim.x;
    if (which == 0) {
        for (int i = blockIdx.x * blockDim.x + threadIdx.x; i < n4; i += stride) {
            float4 v = ((const float4*)src)[i];
            uint32_t h0 = pack_f16(v.x, v.y);
            uint32_t h1 = pack_f16(v.z, v.w);
            __half2 h0h = *reinterpret_cast<__half2*>(&h0);
            __half2 h1h = *reinterpret_cast<__half2*>(&h1);
            float l0 = v.x - __half2float(__low2half(h0h));
            float l1 = v.y - __half2float(__high2half(h0h));
            float l2 = v.z - __half2float(__low2half(h1h));
            float l3 = v.w - __half2float(__high2half(h1h));
            g_xhi[2 * i]     = h0;
            g_xhi[2 * i + 1] = h1;
            g_xlo[2 * i]     = pack_f16(l0, l1);
            g_xlo[2 * i + 1] = pack_f16(l2, l3);
        }
    } else {
        for (int i = blockIdx.x * blockDim.x + threadIdx.x; i < n4; i += stride) {
            float4 v = ((const float4*)src)[i];
            g_whi[2 * i]     = pack_f16(v.x, v.y);
            g_whi[2 * i + 1] = pack_f16(v.z, v.w);
        }
    }
}

// ============================================================================
// wx_mma: y[m,n] = sum_k x[m,k]*Wih[n,k] + bias[n].
// fp16 2-MMA: (xhi + xlo) * W_fp16, fp32 accumulate.
// CTA tile 128m x 128n, BK=32, 512 threads (16 warps, warp tile 32x32).
// Stage: Ahi/Alo 128x32 fp16 (80B rows) + B 128x32 fp16 = 30720 B, x2 buf.
// ============================================================================
#define STG_BYTES 30720
#define A_LO_OFF  10240
#define B_OFF     20480

__global__ __launch_bounds__(512, 1)
void wx_mma(const float* __restrict__ bias, float* __restrict__ y)
{
    extern __shared__ __align__(16) char smem[];
    const uint32_t sbase = smem_u32(smem);

    const int tid  = threadIdx.x;
    const int wid  = tid >> 5;
    const int lane = tid & 31;
    const int g    = lane >> 2;
    const int t    = lane & 3;
    const int wm   = wid & 3;
    const int wn   = wid >> 2;
    const int m0   = blockIdx.y * 128;
    const int n0   = blockIdx.x * 128;

    float acc[2][4][4];
#pragma unroll
    for (int mf = 0; mf < 2; mf++)
#pragma unroll
        for (int nf = 0; nf < 4; nf++)
#pragma unroll
            for (int c = 0; c < 4; c++) acc[mf][nf][c] = 0.0f;

    auto issue = [&](int st) {
        const uint32_t d = sbase + (st & 1) * STG_BYTES;
        const int k0 = st * 32;
        // A: 1024 x 16B tasks (hi then lo)
#pragma unroll
        for (int r = 0; r < 2; r++) {
            int id   = tid + 512 * r;
            int part = id >> 9;
            int rem  = id & 511;
            int row  = rem >> 2;
            int seg  = rem & 3;
            const unsigned* srcb = part ? g_xlo : g_xhi;
            const char* src = (const char*)(srcb +
                ((size_t)(m0 + row) * 1024 + k0) / 2) + seg * 16;
            cp_async16(d + part * A_LO_OFF + row * 80 + seg * 16, src);
        }
        // B: 512 x 16B tasks (single fp16 W)
        {
            int row = tid >> 2;
            int seg = tid & 3;
            const char* src = (const char*)(g_whi +
                ((size_t)(n0 + row) * 1024 + k0) / 2) + seg * 16;
            cp_async16(d + B_OFF + row * 80 + seg * 16, src);
        }
        asm volatile("cp.async.commit_group;" ::: "memory");
    };

    issue(0);
    for (int i = 0; i < 32; i++) {
        if (i + 1 < 32) {
            issue(i + 1);
            asm volatile("cp.async.wait_group 1;" ::: "memory");
        } else {
            asm volatile("cp.async.wait_group 0;" ::: "memory");
        }
        __syncthreads();

        const char* sm  = smem + (i & 1) * STG_BYTES;
        const char* Ahi = sm;
        const char* Alo = sm + A_LO_OFF;
        const char* Bsm = sm + B_OFF;

#pragma unroll
        for (int ks = 0; ks < 32; ks += 16) {
            const int colb = (ks + t * 2) * 2;
            uint32_t ah[2][4], al[2][4];
#pragma unroll
            for (int mf = 0; mf < 2; mf++) {
                int r0 = (wm * 32 + mf * 16 + g) * 80;
                int r1 = r0 + 8 * 80;
                ah[mf][0] = *(const uint32_t*)(Ahi + r0 + colb);
                ah[mf][1] = *(const uint32_t*)(Ahi + r1 + colb);
                ah[mf][2] = *(const uint32_t*)(Ahi + r0 + colb + 16);
                ah[mf][3] = *(const uint32_t*)(Ahi + r1 + colb + 16);
                al[mf][0] = *(const uint32_t*)(Alo + r0 + colb);
                al[mf][1] = *(const uint32_t*)(Alo + r1 + colb);
                al[mf][2] = *(const uint32_t*)(Alo + r0 + colb + 16);
                al[mf][3] = *(const uint32_t*)(Alo + r1 + colb + 16);
            }
            uint32_t bh[4][2];
#pragma unroll
            for (int nf = 0; nf < 4; nf++) {
                int nr = (wn * 32 + nf * 8 + g) * 80;
                bh[nf][0] = *(const uint32_t*)(Bsm + nr + colb);
                bh[nf][1] = *(const uint32_t*)(Bsm + nr + colb + 16);
            }
#pragma unroll
            for (int mf = 0; mf < 2; mf++)
#pragma unroll
                for (int nf = 0; nf < 4; nf++) {
                    float* c = acc[mf][nf];
                    mma_f16(c[0], c[1], c[2], c[3],
                            ah[mf][0], ah[mf][1], ah[mf][2], ah[mf][3],
                            bh[nf][0], bh[nf][1]);
                    mma_f16(c[0], c[1], c[2], c[3],
                            al[mf][0], al[mf][1], al[mf][2], al[mf][3],
                            bh[nf][0], bh[nf][1]);
                }
        }
        __syncthreads();
    }

#pragma unroll
    for (int mf = 0; mf < 2; mf++) {
        int m = m0 + wm * 32 + mf * 16 + g;
#pragma unroll
        for (int nf = 0; nf < 4; nf++) {
            int n = n0 + wn * 32 + nf * 8 + t * 2;
            float2 bv = *(const float2*)(bias + n);
            float* c = acc[mf][nf];
            *(float2*)(y + (size_t)m * H_ + n) =
                make_float2(c[0] + bv.x, c[1] + bv.y);
            *(float2*)(y + (size_t)(m + 8) * H_ + n) =
                make_float2(c[2] + bv.x, c[3] + bv.y);
        }
    }
}

// ============================================================================
// Sync (R14, known good): entry rendezvous + per-bg monotonic step counter.
// ============================================================================
__device__ unsigned g_cnt[4 * 32];
__device__ unsigned g_gen[4 * 32];
__device__ unsigned g_step[4 * 32];

__device__ __forceinline__ void rendezvous(int bg, unsigned nb) {
    __syncthreads();
    if (threadIdx.x == 0) {
        unsigned* cnt = &g_cnt[bg * 32];
        unsigned* gen = &g_gen[bg * 32];
        unsigned g;
        asm volatile("ld.global.acquire.gpu.u32 %0, [%1];" : "=r"(g) : "l"(gen));
        unsigned prev;
        asm volatile("atom.global.acq_rel.gpu.add.u32 %0, [%1], %2;"
                     : "=r"(prev) : "l"(cnt), "r"(1u));
        if (prev == nb - 1) {
            asm volatile("st.global.relaxed.gpu.u32 [%0], %1;" :: "l"(cnt), "r"(0u));
            asm volatile("st.global.release.gpu.u32 [%0], %1;" :: "l"(gen), "r"(g + 1u));
        } else {
            unsigned cur;
            do {
                asm volatile("ld.global.acquire.gpu.u32 %0, [%1];" : "=r"(cur) : "l"(gen));
            } while (cur == g);
        }
    }
    __syncthreads();
}

__device__ __forceinline__ void poll_ge(const unsigned* p, unsigned tgt) {
    unsigned v;
    do {
        asm volatile("ld.global.acquire.gpu.u32 %0, [%1];" : "=r"(v) : "l"(p));
    } while ((int)(v - tgt) < 0);
}

// ============================================================================
// Persistent recurrence (R14 verbatim): split-bf16 HMMA, two independent
// half-pipelines (kw0: K[0,512), kw1: K[512,1024)), named barriers.
// ============================================================================
#define WHI_OFF 0
#define WLO_OFF 66048
#define HHI_OFF 132096
#define HLO_OFF 165120
#define RED_OFF 198144
#define RNN_SMEM 200192

__global__ __launch_bounds__(256, 1)
void rnn_persistent(const float* __restrict__ h0,
                    const float* __restrict__ Whh,
                    const float* __restrict__ bias,
                    float* __restrict__ y,
                    float* __restrict__ hlast)
{
    extern __shared__ __align__(16) char smem[];
    const uint32_t sb = smem_u32(smem);
    __shared__ unsigned sh_base;

    const int tid  = threadIdx.x;
    const int w    = tid >> 5;
    const int lane = tid & 31;
    const int nf   = w & 3;
    const int kw   = w >> 2;
    const int htid = tid & 127;
    const int ft_id = blockIdx.x;
    const int bg_id = blockIdx.y;
    const int ftile = ft_id * 32;
    const int bg    = bg_id * 16;

    unsigned* step_cnt = &g_step[bg_id * 32];
    if (tid == 0) {
        unsigned b0;
        asm volatile("ld.global.relaxed.gpu.u32 %0, [%1];" : "=r"(b0) : "l"(step_cnt));
        sh_base = b0;
    }

    // ---- one-time: Whh slice -> smem split bf16, 2064B padded rows ----
    {
        const int r = tid >> 3;
        const int part = tid & 7;
        const float* src = Whh + (size_t)(ftile + r) * H_ + part * 128;
        char* dhi = smem + WHI_OFF + r * 2064 + part * 256;
        char* dlo = smem + WLO_OFF + r * 2064 + part * 256;
#pragma unroll
        for (int u = 0; u < 32; u++) {
            float4 v = *(const float4*)(src + u * 4);
            uint32_t h0p = pack_bf16(v.x, v.y);
            uint32_t h1p = pack_bf16(v.z, v.w);
            float l0 = v.x - __uint_as_float(h0p << 16);
            float l1 = v.y - __uint_as_float(h0p & 0xFFFF0000u);
            float l2 = v.z - __uint_as_float(h1p << 16);
            float l3 = v.w - __uint_as_float(h1p & 0xFFFF0000u);
            *(uint2*)(dhi + u * 8) = make_uint2(h0p, h1p);
            *(uint2*)(dlo + u * 8) = make_uint2(pack_bf16(l0, l1), pack_bf16(l2, l3));
        }
    }

    // ---- one-time: ft0 CTA converts h0 (its bg's 16 rows) into g_hb[0] ----
    if (ft_id == 0) {
        const int r = tid >> 4;
        const int part = tid & 15;
        const float* src = h0 + (size_t)(bg + r) * H_ + part * 64;
        unsigned* dhi = &g_hb[0][0][(bg + r) * 512 + part * 32];
        unsigned* dlo = &g_hb[0][1][(bg + r) * 512 + part * 32];
#pragma unroll
        for (int u = 0; u < 16; u++) {
            float4 v = *(const float4*)(src + u * 4);
            uint32_t h0p = pack_bf16(v.x, v.y);
            uint32_t h1p = pack_bf16(v.z, v.w);
            float l0 = v.x - __uint_as_float(h0p << 16);
            float l1 = v.y - __uint_as_float(h0p & 0xFFFF0000u);
            float l2 = v.z - __uint_as_float(h1p << 16);
            float l3 = v.w - __uint_as_float(h1p & 0xFFFF0000u);
            *(uint2*)(dhi + u * 2) = make_uint2(h0p, h1p);
            *(uint2*)(dlo + u * 2) = make_uint2(pack_bf16(l0, l1), pack_bf16(l2, l3));
        }
    }

    // ---- output mapping ----
    const int mq = lane >> 2;
    const int q  = lane & 3;
    const int fgn  = ftile + nf * 8 + q * 2;
    const int rowA = bg + mq;
    const int rowB = bg + mq + 8;
    float2 bias2 = *(const float2*)(bias + fgn);
    float* yA = y + (size_t)rowA * SH_ + fgn;
    float* yB = y + (size_t)rowB * SH_ + fgn;
    float2 wx2 = (kw == 0) ? *(float2*)yA : *(float2*)yB;

    // ---- ldmatrix base addresses ----
    const uint32_t aHiB = sb + HHI_OFF + (uint32_t)(lane & 15) * 2064 +
                          (uint32_t)((lane >> 4) << 4);
    const uint32_t aLoB = aHiB + (HLO_OFF - HHI_OFF);
    const int bl = lane & 15;
    const uint32_t bHiB = sb + WHI_OFF +
                          (uint32_t)(nf * 8 + (bl & 7)) * 2064 +
                          (uint32_t)(((bl >> 3) & 1) << 4);
    const uint32_t bLoB = bHiB + (WLO_OFF - WHI_OFF);

    float2* bufA = (float2*)(smem + RED_OFF);        // kw0 -> kw1 (rowB partials)
    float2* bufB = bufA + 128;                       // kw1 -> kw0 (rowA partials)
    const int slot = (nf * 8 + mq) * 4 + q;

    const int kbase = kw * 512;
    const int barid = 1 + kw;

    rendezvous(bg_id, 32);
    const unsigned base = sh_base;

    for (int s = 0; s < S_; s++) {
        const int p = s & 1;

        if (s > 0) {
            if (htid == 0) poll_ge(step_cnt, base + 32u * (unsigned)s);
            HALF_BAR(barid);
        }

#pragma unroll
        for (int c = 0; c < 2; c++) {
            const int koffB = (kbase + c * 256) * 2;
#pragma unroll
            for (int r = 0; r < 8; r++) {
                int idx   = r * 128 + htid;
                int split = idx >> 9;
                int rem   = idx & 511;
                int row   = rem >> 5;
                int seg   = rem & 31;
                const char* src = (const char*)g_hb[p][split] +
                                  (size_t)(bg + row) * 2048 + koffB + seg * 16;
                cp_async16(sb + (split ? HLO_OFF : HHI_OFF) +
                           (uint32_t)(row * 2064 + koffB + seg * 16), src);
            }
            asm volatile("cp.async.commit_group;" ::: "memory");
        }

        float c0 = 0.f, c1 = 0.f, c2 = 0.f, c3 = 0.f;

#pragma unroll
        for (int c = 0; c < 2; c++) {
            if (c == 0) asm volatile("cp.async.wait_group 1;" ::: "memory");
            else        asm volatile("cp.async.wait_group 0;" ::: "memory");
            HALF_BAR(barid);

            const int kc = kbase + c * 256;
#pragma unroll 4
            for (int i = 0; i < 16; i++) {
                const uint32_t kb = (uint32_t)(kc + i * 16) * 2;
                uint32_t ah0, ah1, ah2, ah3, al0, al1, al2, al3;
                uint32_t bh0, bh1, blo0, blo1;
                ldsm_x4(ah0, ah1, ah2, ah3, aHiB + kb);
                ldsm_x4(al0, al1, al2, al3, aLoB + kb);
                ldsm_x2(bh0, bh1, bHiB + kb);
                ldsm_x2(blo0, blo1, bLoB + kb);
                mma_bf16(c0, c1, c2, c3, ah0, ah1, ah2, ah3, bh0, bh1);
                mma_bf16(c0, c1, c2, c3, al0, al1, al2, al3, bh0, bh1);
                mma_bf16(c0, c1, c2, c3, ah0, ah1, ah2, ah3, blo0, blo1);
            }
        }

        // ---- symmetric partial exchange ----
        if (kw == 0) bufA[slot] = make_float2(c2, c3);
        else         bufB[slot] = make_float2(c0, c1);
        __syncthreads();

        // ---- writeback: kw0 rowA, kw1 rowB ----
        const int p1 = (s + 1) & 1;
        if (kw == 0) {
            float2 o = bufB[slot];
            float v0 = tanhf(wx2.x + c0 + o.x + bias2.x);
            float v1 = tanhf(wx2.y + c1 + o.y + bias2.y);
            float* ysA = yA + (size_t)s * H_;
            *(float2*)ysA = make_float2(v0, v1);
            uint32_t hp = pack_bf16(v0, v1);
            float l0 = v0 - __uint_as_float(hp << 16);
            float l1 = v1 - __uint_as_float(hp & 0xFFFF0000u);
            g_hb[p1][0][rowA * 512 + (fgn >> 1)] = hp;
            g_hb[p1][1][rowA * 512 + (fgn >> 1)] = pack_bf16(l0, l1);
            if (s == S_ - 1)
                *(float2*)(hlast + (size_t)rowA * H_ + fgn) = make_float2(v0, v1);
            else
                wx2 = *(float2*)(ysA + H_);
        } else {
            float2 o = bufA[slot];
            float v0 = tanhf(wx2.x + c2 + o.x + bias2.x);
            float v1 = tanhf(wx2.y + c3 + o.y + bias2.y);
            float* ysB = yB + (size_t)s * H_;
            *(float2*)ysB = make_float2(v0, v1);
            uint32_t hp = pack_bf16(v0, v1);
            float l0 = v0 - __uint_as_float(hp << 16);
            float l1 = v1 - __uint_as_float(hp & 0xFFFF0000u);
            g_hb[p1][0][rowB * 512 + (fgn >> 1)] = hp;
            g_hb[p1][1][rowB * 512 + (fgn >> 1)] = pack_bf16(l0, l1);
            if (s == S_ - 1)
                *(float2*)(hlast + (size_t)rowB * H_ + fgn) = make_float2(v0, v1);
            else
                wx2 = *(float2*)(ysB + H_);
        }

        // ---- publish: fire-and-forget arrive ----
        __syncthreads();
        if (tid == 0 && s < S_ - 1) {
            asm volatile("red.global.release.gpu.add.u32 [%0], %1;"
                         :: "l"(step_cnt), "r"(1u) : "memory");
        }
    }
}

// ============================================================================
// Launch: 4 graph nodes. Inputs: x, h, Wih_w, Wih_b, Whh_w, Whh_b.
// Output: y [B,S,H] followed by h_last [B,H].
// ============================================================================
extern "C" void kernel_launch(void* const* d_in, const int* in_sizes, int n_in,
                              void* d_out, int out_size)
{
    const float* x     = (const float*)d_in[0];
    const float* h0    = (const float*)d_in[1];
    const float* Wih_w = (const float*)d_in[2];
    const float* Wih_b = (const float*)d_in[3];
    const float* Whh_w = (const float*)d_in[4];
    const float* Whh_b = (const float*)d_in[5];

    float* y     = (float*)d_out;
    float* hlast = y + (size_t)B_ * S_ * H_;

    const int mma_smem = 2 * STG_BYTES;   // 61440
    cudaFuncSetAttribute(wx_mma, cudaFuncAttributeMaxDynamicSharedMemorySize,
                         mma_smem);
    cudaFuncSetAttribute(rnn_persistent,
                         cudaFuncAttributeMaxDynamicSharedMemorySize, RNN_SMEM);

    cvt_split<<<8192, 256>>>(x, 0, 16777216);      // x: 16M float4 -> fp16 hi/lo
    cvt_split<<<1024, 256>>>(Wih_w, 1, 262144);    // W: fp16 single
    wx_mma<<<dim3(8, 512), 512, mma_smem>>>(Wih_b, y);
    rnn_persistent<<<dim3(32, 4), 256, RNN_SMEM>>>(h0, Whh_w, Whh_b, y, hlast);
}